// round 1
// baseline (speedup 1.0000x reference)
#include <cuda_runtime.h>
#include <cuda_bf16.h>
#include <cstdint>

// Problem constants (fixed shapes)
#define DD   256   // feature dim
#define KK   256   // num centers
#define OUTD 128   // output dim

// ---------------- constant precompute scratch (device globals) ----------------
__device__ __align__(16) float          g_s[DD];            // relu(sigma)
__device__ __align__(16) float          g_c2[KK];           // sum_d s_d * center[k,d]^2
__device__ __align__(16) float          g_SV[OUTD];         // sum_k V[k,o]
__device__ __align__(16) float          g_Bp[OUTD];         // relu(W0)+sum relu(Wk) - sum c2*V
__device__ __align__(16) __nv_bfloat16  g_M2T[OUTD * DD];   // [o][d] = 2 * sum_k center[k,d]*V[k,o]

// ---------------- prep kernel 1: s and c2 ----------------
__global__ void prep1_kernel(const float* __restrict__ sigma,
                             const float* __restrict__ center) {
    __shared__ float s_sh[DD];
    int tid = threadIdx.x;
    float s = fmaxf(sigma[tid], 0.0f);
    g_s[tid] = s;
    s_sh[tid] = s;
    __syncthreads();

    int warp = tid >> 5, lane = tid & 31;
    for (int k = warp * 32; k < warp * 32 + 32; k++) {
        const float4* cp = reinterpret_cast<const float4*>(center + k * DD + lane * 8);
        float4 c0 = cp[0], c1 = cp[1];
        int db = lane * 8;
        float part = s_sh[db + 0] * c0.x * c0.x + s_sh[db + 1] * c0.y * c0.y
                   + s_sh[db + 2] * c0.z * c0.z + s_sh[db + 3] * c0.w * c0.w
                   + s_sh[db + 4] * c1.x * c1.x + s_sh[db + 5] * c1.y * c1.y
                   + s_sh[db + 6] * c1.z * c1.z + s_sh[db + 7] * c1.w * c1.w;
        #pragma unroll
        for (int off = 16; off; off >>= 1)
            part += __shfl_xor_sync(0xffffffffu, part, off);
        if (lane == 0) g_c2[k] = part;
    }
}

// ---------------- prep kernel 2: M2T, SV, Bp (one block per output col) -------
__global__ void prep2_kernel(const float* __restrict__ center,
                             const float* __restrict__ width,
                             const float* __restrict__ wout) {
    int o = blockIdx.x;
    int tid = threadIdx.x;  // serves as both k and d index
    __shared__ float Vk[KK];
    __shared__ float red0[KK], red1[KK], red2[KK];

    float wk = fmaxf(width[tid], 0.0f);
    float wo = fmaxf(wout[(1 + tid) * OUTD + o], 0.0f);
    float v  = wk * wo;
    Vk[tid]   = v;
    red0[tid] = v;               // -> SV
    red1[tid] = wo;              // -> SW
    red2[tid] = g_c2[tid] * v;   // -> CV
    __syncthreads();

    for (int off = 128; off; off >>= 1) {
        if (tid < off) {
            red0[tid] += red0[tid + off];
            red1[tid] += red1[tid + off];
            red2[tid] += red2[tid + off];
        }
        __syncthreads();
    }
    if (tid == 0) {
        g_SV[o] = red0[0];
        g_Bp[o] = fmaxf(wout[o], 0.0f) + red1[0] - red2[0];
    }

    // M2T[o][d] = 2 * sum_k center[k][d] * V[k]
    float m = 0.0f;
    #pragma unroll 8
    for (int k = 0; k < KK; k++)
        m = fmaf(center[k * DD + tid], Vk[k], m);
    g_M2T[o * DD + tid] = __float2bfloat16(2.0f * m);
}

// ---------------- helpers ----------------
__device__ __forceinline__ uint32_t pack_bf16x2(float lo, float hi) {
    uint32_t r;
    asm("cvt.rn.bf16x2.f32 %0, %1, %2;" : "=r"(r) : "f"(hi), "f"(lo));
    return r;
}

__device__ __forceinline__ void mma16816(float* c, uint32_t a0, uint32_t a1,
                                         uint32_t a2, uint32_t a3,
                                         uint32_t b0, uint32_t b1) {
    asm volatile(
        "mma.sync.aligned.m16n8k16.row.col.f32.bf16.bf16.f32 "
        "{%0,%1,%2,%3}, {%4,%5,%6,%7}, {%8,%9}, {%0,%1,%2,%3};"
        : "+f"(c[0]), "+f"(c[1]), "+f"(c[2]), "+f"(c[3])
        : "r"(a0), "r"(a1), "r"(a2), "r"(a3), "r"(b0), "r"(b1));
}

// ---------------- main kernel: out = Bp - x2*SV + xs @ M2 ----------------
// Block: 256 threads = 8 warps. Warp grid 4(m) x 2(n); warp tile 32x64.
// Block tile: 128 rows x 128 cols (all of OUT). No shared memory in main loop.
__global__ void __launch_bounds__(256, 2)
rbf_main_kernel(const float* __restrict__ x, float* __restrict__ out) {
    const int tid  = threadIdx.x;
    const int warp = tid >> 5;
    const int lane = tid & 31;
    const int warp_m = warp >> 1;     // 0..3
    const int warp_n = warp & 1;      // 0..1
    const int quad  = lane >> 2;      // 0..7  (groupID)
    const int qlane = lane & 3;       // 0..3  (threadID in group)

    const int row_base = blockIdx.x * 128 + warp_m * 32;
    const int col_base = warp_n * 64;

    float acc[2][8][4];
    #pragma unroll
    for (int mt = 0; mt < 2; mt++)
        #pragma unroll
        for (int nt = 0; nt < 8; nt++)
            #pragma unroll
            for (int i = 0; i < 4; i++) acc[mt][nt][i] = 0.0f;

    float x2p[2][2] = {{0.f, 0.f}, {0.f, 0.f}};  // [mtile][rowhalf]

    #pragma unroll 4
    for (int k0 = 0; k0 < DD; k0 += 16) {
        const int kb = k0 + 2 * qlane;
        const float2 s0 = *reinterpret_cast<const float2*>(g_s + kb);
        const float2 s1 = *reinterpret_cast<const float2*>(g_s + kb + 8);

        // B fragments for 8 n-tiles (constant matrix, L1/L2 resident)
        uint32_t bfr[8][2];
        #pragma unroll
        for (int nt = 0; nt < 8; nt++) {
            const __nv_bfloat16* bp = g_M2T + (size_t)(col_base + nt * 8 + quad) * DD + kb;
            bfr[nt][0] = *reinterpret_cast<const uint32_t*>(bp);
            bfr[nt][1] = *reinterpret_cast<const uint32_t*>(bp + 8);
        }

        #pragma unroll
        for (int mt = 0; mt < 2; mt++) {
            const float* xr0 = x + (size_t)(row_base + mt * 16 + quad) * DD + kb;
            const float* xr1 = xr0 + 8 * DD;
            float2 v00 = *reinterpret_cast<const float2*>(xr0);
            float2 v01 = *reinterpret_cast<const float2*>(xr0 + 8);
            float2 v10 = *reinterpret_cast<const float2*>(xr1);
            float2 v11 = *reinterpret_cast<const float2*>(xr1 + 8);

            float xs00x = v00.x * s0.x, xs00y = v00.y * s0.y;
            float xs01x = v01.x * s1.x, xs01y = v01.y * s1.y;
            float xs10x = v10.x * s0.x, xs10y = v10.y * s0.y;
            float xs11x = v11.x * s1.x, xs11y = v11.y * s1.y;

            x2p[mt][0] += xs00x * v00.x + xs00y * v00.y + xs01x * v01.x + xs01y * v01.y;
            x2p[mt][1] += xs10x * v10.x + xs10y * v10.y + xs11x * v11.x + xs11y * v11.y;

            uint32_t a0 = pack_bf16x2(xs00x, xs00y);  // row r0, k = kb..kb+1
            uint32_t a1 = pack_bf16x2(xs10x, xs10y);  // row r0+8
            uint32_t a2 = pack_bf16x2(xs01x, xs01y);  // row r0, k = kb+8..kb+9
            uint32_t a3 = pack_bf16x2(xs11x, xs11y);  // row r0+8

            #pragma unroll
            for (int nt = 0; nt < 8; nt++)
                mma16816(acc[mt][nt], a0, a1, a2, a3, bfr[nt][0], bfr[nt][1]);
        }
    }

    // complete x2 across the quad (each qlane covered 1/4 of the k's)
    float x2f[2][2];
    #pragma unroll
    for (int mt = 0; mt < 2; mt++)
        #pragma unroll
        for (int h = 0; h < 2; h++) {
            float v = x2p[mt][h];
            v += __shfl_xor_sync(0xffffffffu, v, 1);
            v += __shfl_xor_sync(0xffffffffu, v, 2);
            x2f[mt][h] = v;
        }

    // epilogue: out = acc + Bp[n] - x2*SV[n]
    #pragma unroll
    for (int nt = 0; nt < 8; nt++) {
        const int n = col_base + nt * 8 + 2 * qlane;
        const float2 bp = *reinterpret_cast<const float2*>(g_Bp + n);
        const float2 sv = *reinterpret_cast<const float2*>(g_SV + n);
        #pragma unroll
        for (int mt = 0; mt < 2; mt++) {
            const int r0 = row_base + mt * 16 + quad;
            float2 o0, o1;
            o0.x = acc[mt][nt][0] + bp.x - x2f[mt][0] * sv.x;
            o0.y = acc[mt][nt][1] + bp.y - x2f[mt][0] * sv.y;
            o1.x = acc[mt][nt][2] + bp.x - x2f[mt][1] * sv.x;
            o1.y = acc[mt][nt][3] + bp.y - x2f[mt][1] * sv.y;
            *reinterpret_cast<float2*>(out + (size_t)r0 * OUTD + n)       = o0;
            *reinterpret_cast<float2*>(out + (size_t)(r0 + 8) * OUTD + n) = o1;
        }
    }
}

// ---------------- launcher ----------------
extern "C" void kernel_launch(void* const* d_in, const int* in_sizes, int n_in,
                              void* d_out, int out_size) {
    const float* x      = (const float*)d_in[0];  // [N, D]
    const float* center = (const float*)d_in[1];  // [K, D]
    const float* sigma  = (const float*)d_in[2];  // [D]
    const float* width  = (const float*)d_in[3];  // [K]
    const float* wout   = (const float*)d_in[4];  // [1+K, OUT]
    float* out = (float*)d_out;

    const int N = in_sizes[0] / DD;

    prep1_kernel<<<1, 256>>>(sigma, center);
    prep2_kernel<<<OUTD, 256>>>(center, width, wout);
    rbf_main_kernel<<<N / 128, 256>>>(x, out);
}

// round 2
// speedup vs baseline: 1.5416x; 1.5416x over previous
#include <cuda_runtime.h>
#include <cuda_bf16.h>
#include <cstdint>

// Problem constants (fixed shapes)
#define DD   256   // feature dim
#define KK   256   // num centers
#define OUTD 128   // output dim

// ---------------- constant precompute scratch (device globals) ----------------
__device__ __align__(16) float          g_c2[KK];            // sum_d s_d * center[k,d]^2
__device__ __align__(16) float          g_SV[OUTD];          // sum_k V[k,o]
__device__ __align__(16) float          g_Bp[OUTD];          // relu(W0)+sum relu(Wk) - sum c2*V
// Packed s: [k16 (16)][lane (32)][4 floats] = s at {kb, kb+1, kb+8, kb+9}, kb=k16*16+2*(lane&3)
__device__ __align__(16) float          g_Spk[16 * 32 * 4];
// Packed B fragments (bf16): uint4 index = (k16*8 + j)*32 + lane, j covers n-tiles {2j, 2j+1}
// u32 within uint4: (nt&1)*2 + i, i=0 -> b0 (k=2l..2l+1), i=1 -> b1 (k+8)
__device__ __align__(16) __nv_bfloat16  g_Bpk[16 * 8 * 32 * 4 * 2];   // 64KB

// ---------------- prep kernel 1: c2 (one block per center) + packed s ----------
__global__ void prep1_kernel(const float* __restrict__ sigma,
                             const float* __restrict__ center) {
    const int k = blockIdx.x;
    const int t = threadIdx.x;
    __shared__ float s_sh[DD];
    __shared__ float red[8];

    float s = fmaxf(sigma[t], 0.0f);
    s_sh[t] = s;
    __syncthreads();

    // block 0 additionally writes the packed s layout
    if (k == 0) {
        for (int idx = t; idx < 16 * 32; idx += 256) {
            int k16 = idx >> 5, lane = idx & 31, ql = lane & 3;
            int kb = k16 * 16 + 2 * ql;
            float4 v = make_float4(s_sh[kb], s_sh[kb + 1], s_sh[kb + 8], s_sh[kb + 9]);
            reinterpret_cast<float4*>(g_Spk)[idx] = v;
        }
    }

    float c = center[k * DD + t];
    float part = s * c * c;
    #pragma unroll
    for (int off = 16; off; off >>= 1)
        part += __shfl_xor_sync(0xffffffffu, part, off);
    int warp = t >> 5, lane = t & 31;
    if (lane == 0) red[warp] = part;
    __syncthreads();
    if (t == 0) {
        float sum = red[0] + red[1] + red[2] + red[3]
                  + red[4] + red[5] + red[6] + red[7];
        g_c2[k] = sum;
    }
}

// ---------------- packed-B writer ----------------
__device__ __forceinline__ void write_Bpk(int o, int d, float val) {
    int nt = o >> 3, q = o & 7;
    int k16 = d >> 4, r = d & 15;
    int i = r >> 3, l = (r & 7) >> 1, h = r & 1;
    int lane = q * 4 + l;
    int u32idx = ((k16 * 8 + (nt >> 1)) * 32 + lane) * 4 + (nt & 1) * 2 + i;
    g_Bpk[u32idx * 2 + h] = __float2bfloat16(val);
}

// ---------------- prep kernel 2: M2 (packed), SV, Bp — 2 output cols per block -
__global__ void prep2_kernel(const float* __restrict__ center,
                             const float* __restrict__ width,
                             const float* __restrict__ wout) {
    const int o0 = blockIdx.x * 2;
    const int o1 = o0 + 1;
    const int t = threadIdx.x;   // k index for reductions, d index for M2
    __shared__ float V0[KK], V1[KK];
    __shared__ float red[6][8];

    float wk = fmaxf(width[t], 0.0f);
    float w0 = fmaxf(wout[(1 + t) * OUTD + o0], 0.0f);
    float w1 = fmaxf(wout[(1 + t) * OUTD + o1], 0.0f);
    float v0 = wk * w0, v1 = wk * w1;
    V0[t] = v0; V1[t] = v1;
    float c2 = g_c2[t];

    float r0 = v0, r1 = w0, r2 = c2 * v0;
    float r3 = v1, r4 = w1, r5 = c2 * v1;
    #pragma unroll
    for (int off = 16; off; off >>= 1) {
        r0 += __shfl_xor_sync(0xffffffffu, r0, off);
        r1 += __shfl_xor_sync(0xffffffffu, r1, off);
        r2 += __shfl_xor_sync(0xffffffffu, r2, off);
        r3 += __shfl_xor_sync(0xffffffffu, r3, off);
        r4 += __shfl_xor_sync(0xffffffffu, r4, off);
        r5 += __shfl_xor_sync(0xffffffffu, r5, off);
    }
    int warp = t >> 5, lane = t & 31;
    if (lane == 0) {
        red[0][warp] = r0; red[1][warp] = r1; red[2][warp] = r2;
        red[3][warp] = r3; red[4][warp] = r4; red[5][warp] = r5;
    }
    __syncthreads();
    if (t < 2) {
        int o = (t == 0) ? o0 : o1;
        const float* a = red[3 * t];
        const float* b = red[3 * t + 1];
        const float* c = red[3 * t + 2];
        float sv = 0, sw = 0, cv = 0;
        #pragma unroll
        for (int w = 0; w < 8; w++) { sv += a[w]; sw += b[w]; cv += c[w]; }
        g_SV[o] = sv;
        g_Bp[o] = fmaxf(wout[o], 0.0f) + sw - cv;
    }

    // M2[d][o] = 2 * sum_k center[k][d] * V[k][o], for d = t
    float m00 = 0, m01 = 0, m10 = 0, m11 = 0;   // split k for MLP
    #pragma unroll 4
    for (int k = 0; k < KK; k += 2) {
        float ca = center[k * DD + t];
        float cb = center[(k + 1) * DD + t];
        m00 = fmaf(ca, V0[k], m00);
        m10 = fmaf(ca, V1[k], m10);
        m01 = fmaf(cb, V0[k + 1], m01);
        m11 = fmaf(cb, V1[k + 1], m11);
    }
    write_Bpk(o0, t, 2.0f * (m00 + m01));
    write_Bpk(o1, t, 2.0f * (m10 + m11));
}

// ---------------- helpers ----------------
__device__ __forceinline__ uint32_t pack_bf16x2(float lo, float hi) {
    uint32_t r;
    asm("cvt.rn.bf16x2.f32 %0, %1, %2;" : "=r"(r) : "f"(hi), "f"(lo));
    return r;
}

__device__ __forceinline__ void mma16816(float* c, uint32_t a0, uint32_t a1,
                                         uint32_t a2, uint32_t a3,
                                         uint32_t b0, uint32_t b1) {
    asm volatile(
        "mma.sync.aligned.m16n8k16.row.col.f32.bf16.bf16.f32 "
        "{%0,%1,%2,%3}, {%4,%5,%6,%7}, {%8,%9}, {%0,%1,%2,%3};"
        : "+f"(c[0]), "+f"(c[1]), "+f"(c[2]), "+f"(c[3])
        : "r"(a0), "r"(a1), "r"(a2), "r"(a3), "r"(b0), "r"(b1));
}

// ---------------- main kernel: out = Bp - x2*SV + xs @ M2 ----------------
// Block: 256 threads = 8 warps. Warp grid 4(m) x 2(n); warp tile 32x64.
// Block tile: 128 rows x 128 cols. Main loop: 13 LDG/thread/iter, no smem.
__global__ void __launch_bounds__(256, 2)
rbf_main_kernel(const float* __restrict__ x, float* __restrict__ out) {
    const int tid  = threadIdx.x;
    const int warp = tid >> 5;
    const int lane = tid & 31;
    const int warp_m = warp >> 1;     // 0..3
    const int warp_n = warp & 1;      // 0..1
    const int quad  = lane >> 2;      // 0..7
    const int qlane = lane & 3;       // 0..3

    const int row_base = blockIdx.x * 128 + warp_m * 32;
    const int col_base = warp_n * 64;

    float acc[2][8][4];
    #pragma unroll
    for (int mt = 0; mt < 2; mt++)
        #pragma unroll
        for (int nt = 0; nt < 8; nt++)
            #pragma unroll
            for (int i = 0; i < 4; i++) acc[mt][nt][i] = 0.0f;

    float x2p[2][2] = {{0.f, 0.f}, {0.f, 0.f}};  // [mtile][rowhalf]

    const uint4* Bb = reinterpret_cast<const uint4*>(g_Bpk) + warp_n * 128 + lane;
    const float4* Sb = reinterpret_cast<const float4*>(g_Spk) + lane;
    const float* xr0 = x + (size_t)(row_base + quad) * DD + 2 * qlane;          // mt0 row a
    const float* xr2 = xr0 + 16 * DD;                                           // mt1 row a

    #pragma unroll 4
    for (int k16 = 0; k16 < 16; k16++) {
        const int kb = k16 * 16;

        // B fragments: 4x LDG.128, fully coalesced
        uint4 b4[4];
        #pragma unroll
        for (int jj = 0; jj < 4; jj++)
            b4[jj] = Bb[k16 * 256 + jj * 32];

        // packed s: 1x LDG.128 (L1/L2-resident)
        const float4 sv = Sb[k16 * 32];

        #pragma unroll
        for (int mt = 0; mt < 2; mt++) {
            const float* ra = (mt == 0) ? xr0 : xr2;
            const float* rb = ra + 8 * DD;
            float2 v00 = *reinterpret_cast<const float2*>(ra + kb);
            float2 v01 = *reinterpret_cast<const float2*>(ra + kb + 8);
            float2 v10 = *reinterpret_cast<const float2*>(rb + kb);
            float2 v11 = *reinterpret_cast<const float2*>(rb + kb + 8);

            float xs00x = v00.x * sv.x, xs00y = v00.y * sv.y;
            float xs01x = v01.x * sv.z, xs01y = v01.y * sv.w;
            float xs10x = v10.x * sv.x, xs10y = v10.y * sv.y;
            float xs11x = v11.x * sv.z, xs11y = v11.y * sv.w;

            x2p[mt][0] += xs00x * v00.x + xs00y * v00.y + xs01x * v01.x + xs01y * v01.y;
            x2p[mt][1] += xs10x * v10.x + xs10y * v10.y + xs11x * v11.x + xs11y * v11.y;

            uint32_t a0 = pack_bf16x2(xs00x, xs00y);
            uint32_t a1 = pack_bf16x2(xs10x, xs10y);
            uint32_t a2 = pack_bf16x2(xs01x, xs01y);
            uint32_t a3 = pack_bf16x2(xs11x, xs11y);

            #pragma unroll
            for (int jj = 0; jj < 4; jj++) {
                mma16816(acc[mt][2 * jj],     a0, a1, a2, a3, b4[jj].x, b4[jj].y);
                mma16816(acc[mt][2 * jj + 1], a0, a1, a2, a3, b4[jj].z, b4[jj].w);
            }
        }
    }

    // complete x2 across the quad (each qlane covered 1/4 of the k's)
    float x2f[2][2];
    #pragma unroll
    for (int mt = 0; mt < 2; mt++)
        #pragma unroll
        for (int h = 0; h < 2; h++) {
            float v = x2p[mt][h];
            v += __shfl_xor_sync(0xffffffffu, v, 1);
            v += __shfl_xor_sync(0xffffffffu, v, 2);
            x2f[mt][h] = v;
        }

    // epilogue: out = acc + Bp[n] - x2*SV[n]
    #pragma unroll
    for (int nt = 0; nt < 8; nt++) {
        const int n = col_base + nt * 8 + 2 * qlane;
        const float2 bp = *reinterpret_cast<const float2*>(g_Bp + n);
        const float2 sv = *reinterpret_cast<const float2*>(g_SV + n);
        #pragma unroll
        for (int mt = 0; mt < 2; mt++) {
            const int r0 = row_base + mt * 16 + quad;
            float2 o0, o1;
            o0.x = acc[mt][nt][0] + bp.x - x2f[mt][0] * sv.x;
            o0.y = acc[mt][nt][1] + bp.y - x2f[mt][0] * sv.y;
            o1.x = acc[mt][nt][2] + bp.x - x2f[mt][1] * sv.x;
            o1.y = acc[mt][nt][3] + bp.y - x2f[mt][1] * sv.y;
            *reinterpret_cast<float2*>(out + (size_t)r0 * OUTD + n)       = o0;
            *reinterpret_cast<float2*>(out + (size_t)(r0 + 8) * OUTD + n) = o1;
        }
    }
}

// ---------------- launcher ----------------
extern "C" void kernel_launch(void* const* d_in, const int* in_sizes, int n_in,
                              void* d_out, int out_size) {
    const float* x      = (const float*)d_in[0];  // [N, D]
    const float* center = (const float*)d_in[1];  // [K, D]
    const float* sigma  = (const float*)d_in[2];  // [D]
    const float* width  = (const float*)d_in[3];  // [K]
    const float* wout   = (const float*)d_in[4];  // [1+K, OUT]
    float* out = (float*)d_out;

    const int N = in_sizes[0] / DD;

    prep1_kernel<<<KK, 256>>>(sigma, center);
    prep2_kernel<<<OUTD / 2, 256>>>(center, width, wout);
    rbf_main_kernel<<<N / 128, 256>>>(x, out);
}

// round 3
// speedup vs baseline: 1.6757x; 1.0870x over previous
#include <cuda_runtime.h>
#include <cuda_bf16.h>
#include <cstdint>

// Problem constants (fixed shapes)
#define DD   256   // feature dim
#define KK   256   // num centers
#define OUTD 128   // output dim

// ---------------- constant precompute scratch (device globals) ----------------
__device__ __align__(16) float          g_s[DD];             // relu(sigma)
__device__ __align__(16) float          g_c2[KK];            // sum_d s_d * center[k,d]^2
__device__ __align__(16) float          g_SV[OUTD];          // sum_k V[k,o]
__device__ __align__(16) float          g_Bp[OUTD];          // relu(W0)+sum relu(Wk) - sum c2*V
// Packed B fragments (bf16): uint4 index = (k16*8 + j)*32 + lane, j covers n-tiles {2j, 2j+1}
__device__ __align__(16) __nv_bfloat16  g_Bpk[16 * 8 * 32 * 4 * 2];   // 64KB

// ---------------- prep kernel 1: c2 (one block per center) + g_s ----------------
__global__ void prep1_kernel(const float* __restrict__ sigma,
                             const float* __restrict__ center) {
    const int k = blockIdx.x;
    const int t = threadIdx.x;
    __shared__ float red[8];

    float s = fmaxf(sigma[t], 0.0f);
    if (k == 0) g_s[t] = s;

    float c = center[k * DD + t];
    float part = s * c * c;
    #pragma unroll
    for (int off = 16; off; off >>= 1)
        part += __shfl_xor_sync(0xffffffffu, part, off);
    int warp = t >> 5, lane = t & 31;
    if (lane == 0) red[warp] = part;
    __syncthreads();
    if (t == 0) {
        g_c2[k] = red[0] + red[1] + red[2] + red[3]
                + red[4] + red[5] + red[6] + red[7];
    }
}

// ---------------- packed-B writer ----------------
__device__ __forceinline__ void write_Bpk(int o, int d, float val) {
    int nt = o >> 3, q = o & 7;
    int k16 = d >> 4, r = d & 15;
    int i = r >> 3, l = (r & 7) >> 1, h = r & 1;
    int lane = q * 4 + l;
    int u32idx = ((k16 * 8 + (nt >> 1)) * 32 + lane) * 4 + (nt & 1) * 2 + i;
    g_Bpk[u32idx * 2 + h] = __float2bfloat16(val);
}

// ---------------- prep kernel 2: M2 (packed), SV, Bp — 2 output cols per block -
__global__ void prep2_kernel(const float* __restrict__ center,
                             const float* __restrict__ width,
                             const float* __restrict__ wout) {
    const int o0 = blockIdx.x * 2;
    const int o1 = o0 + 1;
    const int t = threadIdx.x;   // k index for reductions, d index for M2
    __shared__ float V0[KK], V1[KK];
    __shared__ float red[6][8];

    float wk = fmaxf(width[t], 0.0f);
    float w0 = fmaxf(wout[(1 + t) * OUTD + o0], 0.0f);
    float w1 = fmaxf(wout[(1 + t) * OUTD + o1], 0.0f);
    float v0 = wk * w0, v1 = wk * w1;
    V0[t] = v0; V1[t] = v1;
    float c2 = g_c2[t];

    float r0 = v0, r1 = w0, r2 = c2 * v0;
    float r3 = v1, r4 = w1, r5 = c2 * v1;
    #pragma unroll
    for (int off = 16; off; off >>= 1) {
        r0 += __shfl_xor_sync(0xffffffffu, r0, off);
        r1 += __shfl_xor_sync(0xffffffffu, r1, off);
        r2 += __shfl_xor_sync(0xffffffffu, r2, off);
        r3 += __shfl_xor_sync(0xffffffffu, r3, off);
        r4 += __shfl_xor_sync(0xffffffffu, r4, off);
        r5 += __shfl_xor_sync(0xffffffffu, r5, off);
    }
    int warp = t >> 5, lane = t & 31;
    if (lane == 0) {
        red[0][warp] = r0; red[1][warp] = r1; red[2][warp] = r2;
        red[3][warp] = r3; red[4][warp] = r4; red[5][warp] = r5;
    }
    __syncthreads();
    if (t < 2) {
        int o = (t == 0) ? o0 : o1;
        const float* a = red[3 * t];
        const float* b = red[3 * t + 1];
        const float* c = red[3 * t + 2];
        float sv = 0, sw = 0, cv = 0;
        #pragma unroll
        for (int w = 0; w < 8; w++) { sv += a[w]; sw += b[w]; cv += c[w]; }
        g_SV[o] = sv;
        g_Bp[o] = fmaxf(wout[o], 0.0f) + sw - cv;
    }

    // M2[d][o] = 2 * sum_k center[k][d] * V[k][o], for d = t
    float m00 = 0, m01 = 0, m10 = 0, m11 = 0;
    #pragma unroll 4
    for (int k = 0; k < KK; k += 2) {
        float ca = center[k * DD + t];
        float cb = center[(k + 1) * DD + t];
        m00 = fmaf(ca, V0[k], m00);
        m10 = fmaf(ca, V1[k], m10);
        m01 = fmaf(cb, V0[k + 1], m01);
        m11 = fmaf(cb, V1[k + 1], m11);
    }
    write_Bpk(o0, t, 2.0f * (m00 + m01));
    write_Bpk(o1, t, 2.0f * (m10 + m11));
}

// ---------------- helpers ----------------
__device__ __forceinline__ uint32_t pack_bf16x2(float lo, float hi) {
    uint32_t r;
    asm("cvt.rn.bf16x2.f32 %0, %1, %2;" : "=r"(r) : "f"(hi), "f"(lo));
    return r;
}

__device__ __forceinline__ void mma16816(float* c, uint32_t a0, uint32_t a1,
                                         uint32_t a2, uint32_t a3,
                                         uint32_t b0, uint32_t b1) {
    asm volatile(
        "mma.sync.aligned.m16n8k16.row.col.f32.bf16.bf16.f32 "
        "{%0,%1,%2,%3}, {%4,%5,%6,%7}, {%8,%9}, {%0,%1,%2,%3};"
        : "+f"(c[0]), "+f"(c[1]), "+f"(c[2]), "+f"(c[3])
        : "r"(a0), "r"(a1), "r"(a2), "r"(a3), "r"(b0), "r"(b1));
}

__device__ __forceinline__ void ldsm_x4(uint32_t& r0, uint32_t& r1,
                                        uint32_t& r2, uint32_t& r3, uint32_t addr) {
    asm volatile("ldmatrix.sync.aligned.m8n8.x4.shared.b16 {%0,%1,%2,%3}, [%4];"
        : "=r"(r0), "=r"(r1), "=r"(r2), "=r"(r3) : "r"(addr));
}

// ---------------- main kernel: out = Bp - x2*SV + xs @ M2 ----------------
// Block: 256 threads = 8 warps. Warp grid 4(m) x 2(n); warp tile 32x64.
// x staged through SMEM (coalesced LDG.128 -> swizzled bf16 tile -> ldmatrix).
__global__ void __launch_bounds__(256, 2)
rbf_main_kernel(const float* __restrict__ x, float* __restrict__ out) {
    __shared__ __align__(16) __nv_bfloat16 xs_sh[128 * 64];  // 16KB, SW128 swizzled
    __shared__ float s_sh[DD];
    __shared__ float x2_sh[128];

    const int tid  = threadIdx.x;
    const int warp = tid >> 5;
    const int lane = tid & 31;
    const int warp_m = warp >> 1;     // 0..3
    const int warp_n = warp & 1;      // 0..1
    const int quad  = lane >> 2;      // 0..7
    const int qlane = lane & 3;       // 0..3

    const int row0 = blockIdx.x * 128;

    // stage s into smem
    s_sh[tid] = g_s[tid];

    float acc[2][8][4];
    #pragma unroll
    for (int mt = 0; mt < 2; mt++)
        #pragma unroll
        for (int nt = 0; nt < 8; nt++)
            #pragma unroll
            for (int i = 0; i < 4; i++) acc[mt][nt][i] = 0.0f;

    // x2 partials: thread owns rows {p*16 + (tid>>4)}, cols slice (tid&15)
    float x2p[8] = {0, 0, 0, 0, 0, 0, 0, 0};

    const int srow = tid >> 4;          // 0..15: row-within-group for staging
    const int scol = tid & 15;          // 0..15: float4 column index for staging
    const uint4* Bb = reinterpret_cast<const uint4*>(g_Bpk) + warp_n * 128 + lane;
    const uint32_t smem_base = (uint32_t)__cvta_generic_to_shared(xs_sh);

    // ldmatrix address (constant across chunks except kbyte)
    const int row_l = warp_m * 32 + (lane & 15);      // + mt*16 added in loop
    const uint32_t lds_swz = (uint32_t)((row_l & 7) << 4);
    const uint32_t lds_koff = (uint32_t)((lane >> 4) << 4);

    __syncthreads();  // s_sh ready

    #pragma unroll 1
    for (int c = 0; c < 4; c++) {
        // -------- staging: x[128][64] fp32 -> xs_sh bf16 (swizzled) --------
        const float4 sv = *reinterpret_cast<const float4*>(s_sh + c * 64 + 4 * scol);
        const float* xb = x + (size_t)(row0 + srow) * DD + c * 64 + 4 * scol;

        __syncthreads();   // previous chunk's compute has consumed xs_sh
        #pragma unroll
        for (int p = 0; p < 8; p++) {
            const int r = p * 16 + srow;
            const float4 v = *reinterpret_cast<const float4*>(xb + (size_t)p * 16 * DD);
            float a = v.x * sv.x, b = v.y * sv.y, cc = v.z * sv.z, d = v.w * sv.w;
            x2p[p] += a * v.x + b * v.y + cc * v.z + d * v.w;
            uint2 packed = make_uint2(pack_bf16x2(a, b), pack_bf16x2(cc, d));
            const uint32_t off = (uint32_t)(r * 128 + ((scol * 8) ^ ((r & 7) << 4)));
            *reinterpret_cast<uint2*>(reinterpret_cast<char*>(xs_sh) + off) = packed;
        }
        __syncthreads();   // xs_sh ready

        // -------- compute: 4 k16 steps --------
        #pragma unroll
        for (int q = 0; q < 4; q++) {
            const int k16 = c * 4 + q;

            uint4 b4[4];
            #pragma unroll
            for (int jj = 0; jj < 4; jj++)
                b4[jj] = Bb[k16 * 256 + jj * 32];

            #pragma unroll
            for (int mt = 0; mt < 2; mt++) {
                const int rl = row_l + mt * 16;
                const uint32_t kbyte = (uint32_t)(q * 32) + lds_koff;
                const uint32_t addr = smem_base + (uint32_t)(rl * 128)
                                    + (kbyte ^ lds_swz);
                uint32_t a0, a1, a2, a3;
                ldsm_x4(a0, a1, a2, a3, addr);

                #pragma unroll
                for (int jj = 0; jj < 4; jj++) {
                    mma16816(acc[mt][2 * jj],     a0, a1, a2, a3, b4[jj].x, b4[jj].y);
                    mma16816(acc[mt][2 * jj + 1], a0, a1, a2, a3, b4[jj].z, b4[jj].w);
                }
            }
        }
    }

    // -------- finalize x2: reduce over 16-lane column groups --------
    #pragma unroll
    for (int p = 0; p < 8; p++) {
        float v = x2p[p];
        v += __shfl_xor_sync(0xffffffffu, v, 1);
        v += __shfl_xor_sync(0xffffffffu, v, 2);
        v += __shfl_xor_sync(0xffffffffu, v, 4);
        v += __shfl_xor_sync(0xffffffffu, v, 8);
        x2p[p] = v;
    }
    if (scol == 0) {
        #pragma unroll
        for (int p = 0; p < 8; p++)
            x2_sh[p * 16 + srow] = x2p[p];
    }
    __syncthreads();

    const float x2a = x2_sh[warp_m * 32 + quad];
    const float x2b = x2_sh[warp_m * 32 + quad + 8];
    const float x2c = x2_sh[warp_m * 32 + 16 + quad];
    const float x2d = x2_sh[warp_m * 32 + 16 + quad + 8];

    // -------- epilogue: out = acc + Bp[n] - x2*SV[n] --------
    const int col_base = warp_n * 64;
    #pragma unroll
    for (int nt = 0; nt < 8; nt++) {
        const int n = col_base + nt * 8 + 2 * qlane;
        const float2 bp = *reinterpret_cast<const float2*>(g_Bp + n);
        const float2 sv = *reinterpret_cast<const float2*>(g_SV + n);
        #pragma unroll
        for (int mt = 0; mt < 2; mt++) {
            const float x2lo = (mt == 0) ? x2a : x2c;
            const float x2hi = (mt == 0) ? x2b : x2d;
            const int r0 = row0 + warp_m * 32 + mt * 16 + quad;
            float2 o0, o1;
            o0.x = acc[mt][nt][0] + bp.x - x2lo * sv.x;
            o0.y = acc[mt][nt][1] + bp.y - x2lo * sv.y;
            o1.x = acc[mt][nt][2] + bp.x - x2hi * sv.x;
            o1.y = acc[mt][nt][3] + bp.y - x2hi * sv.y;
            *reinterpret_cast<float2*>(out + (size_t)r0 * OUTD + n)       = o0;
            *reinterpret_cast<float2*>(out + (size_t)(r0 + 8) * OUTD + n) = o1;
        }
    }
}

// ---------------- launcher ----------------
extern "C" void kernel_launch(void* const* d_in, const int* in_sizes, int n_in,
                              void* d_out, int out_size) {
    const float* x      = (const float*)d_in[0];  // [N, D]
    const float* center = (const float*)d_in[1];  // [K, D]
    const float* sigma  = (const float*)d_in[2];  // [D]
    const float* width  = (const float*)d_in[3];  // [K]
    const float* wout   = (const float*)d_in[4];  // [1+K, OUT]
    float* out = (float*)d_out;

    const int N = in_sizes[0] / DD;

    prep1_kernel<<<KK, 256>>>(sigma, center);
    prep2_kernel<<<OUTD / 2, 256>>>(center, width, wout);
    rbf_main_kernel<<<N / 128, 256>>>(x, out);
}